// round 5
// baseline (speedup 1.0000x reference)
#include <cuda_runtime.h>

#define LOG2E 1.4426950408889634f
#define KG 64            // interpolation grid size
#define JS 8             // j-splits for grid stages
#define NB 96            // persistent blocks (one wave, <=148 SMs)
#define NT 256

// ---------------- scratch ----------------
__device__ float g_conv3[49152];
__device__ float g_conv1[49152];
__device__ float g_v[49152];
__device__ float g_q[49152];
__device__ float g_part[NB * 16];  // per-block stats partials: s3[4] sq3[4] s1[4] sq1[4]
__device__ int   g_m[12];
__device__ float g_qmax[12];
__device__ float g_s0n[12];
__device__ float g_A[12][4096];
__device__ float g_Vnz[12][4096];
__device__ float g_Fp[12][JS][KG];
__device__ float g_Gp[12][JS][KG];
__device__ unsigned g_count;       // zero-init; barrier state
__device__ unsigned g_gen;         // monotonic across launches

__device__ __forceinline__ float ex2(float x) {
    float y; asm("ex2.approx.ftz.f32 %0, %1;" : "=f"(y) : "f"(x)); return y;
}

// sense-reversing grid barrier: read gen, arrive, last resets count then bumps gen
__device__ __forceinline__ void gbar() {
    __syncthreads();
    if (threadIdx.x == 0) {
        __threadfence();
        unsigned my = *(volatile unsigned*)&g_gen;
        unsigned old = atomicAdd(&g_count, 1u);
        if (old == NB - 1) {
            *(volatile unsigned*)&g_count = 0;
            __threadfence();
            atomicAdd(&g_gen, 1u);
        } else {
            while (*(volatile unsigned*)&g_gen == my) __nanosleep(20);
        }
        __threadfence();
    }
    __syncthreads();
}

__global__ void __launch_bounds__(NT, 1)
fused_kernel(const float* __restrict__ x, const float* __restrict__ W3,
             const float* __restrict__ b3, const float* __restrict__ g3,
             const float* __restrict__ be3, const float* __restrict__ W1,
             const float* __restrict__ b1, const float* __restrict__ g1,
             const float* __restrict__ be1, const float* __restrict__ gama,
             float* __restrict__ out) {
    __shared__ float shW3[432];
    __shared__ float shW1[16];
    __shared__ float shB[8];
    __shared__ float smp[8][8];
    __shared__ float shf[8], shs[8];
    __shared__ int   shw[8];
    __shared__ float shsc[4];
    __shared__ __align__(16) float shA[512];
    __shared__ __align__(16) float shU[512];
    __shared__ float shF[KG];
    __shared__ float shP[4][KG];
    __shared__ float shG[3][KG];

    int t = threadIdx.x, b = blockIdx.x;
    int lane = t & 31, wid = t >> 5;

    // ================= stage 1: conv3 + conv1 + stats partials =================
    for (int i = t; i < 432; i += NT) shW3[i] = W3[i];
    if (t < 16) shW1[t] = W1[t];
    if (t < 4)  shB[t] = b3[t];
    if (t >= 4 && t < 8) shB[t] = b1[t - 4];
    __syncthreads();

    {
        int pos = b * 128 + (t & 127);
        int half = t >> 7;            // 0: co {0,1}, 1: co {2,3}
        int co0 = half * 2;
        int d = pos >> 12, p = pos & 4095, h = p >> 6, w = p & 63;

        float acc0 = shB[co0], accA = shB[co0 + 1];
        float c10 = shB[4 + co0], c1A = shB[4 + co0 + 1];

        #pragma unroll
        for (int ci = 0; ci < 4; ci++) {
            const float* xp = x + ci * 12288;
            #pragma unroll
            for (int kd = 0; kd < 3; kd++) {
                int zd = d + kd - 1;
                if ((unsigned)zd >= 3u) continue;
                #pragma unroll
                for (int kh = 0; kh < 3; kh++) {
                    int zh = h + kh - 1;
                    if ((unsigned)zh >= 64u) continue;
                    #pragma unroll
                    for (int kw = 0; kw < 3; kw++) {
                        int zw = w + kw - 1;
                        if ((unsigned)zw >= 64u) continue;
                        float xv = xp[zd * 4096 + zh * 64 + zw];
                        int ki = kd * 9 + kh * 3 + kw;
                        acc0 = fmaf(shW3[(co0 * 4 + ci) * 27 + ki], xv, acc0);
                        accA = fmaf(shW3[((co0 + 1) * 4 + ci) * 27 + ki], xv, accA);
                    }
                }
            }
            float xc = xp[d * 4096 + p];
            c10 = fmaf(shW1[co0 * 4 + ci], xc, c10);
            c1A = fmaf(shW1[(co0 + 1) * 4 + ci], xc, c1A);
        }
        g_conv3[co0 * 12288 + pos]       = acc0;
        g_conv3[(co0 + 1) * 12288 + pos] = accA;
        g_conv1[co0 * 12288 + pos]       = c10;
        g_conv1[(co0 + 1) * 12288 + pos] = c1A;

        float red[8] = {acc0, accA, acc0 * acc0, accA * accA,
                        c10, c1A, c10 * c10, c1A * c1A};
        #pragma unroll
        for (int j = 0; j < 8; j++)
            for (int o = 16; o > 0; o >>= 1)
                red[j] += __shfl_xor_sync(0xffffffffu, red[j], o);
        if (lane == 0) {
            #pragma unroll
            for (int j = 0; j < 8; j++) smp[wid][j] = red[j];
        }
        __syncthreads();
        if (t < 16) {
            int kind = t >> 2, co = t & 3;
            int wbase = (co >> 1) * 4;                 // warps 0-3: co 0,1; warps 4-7: co 2,3
            int r = kind * 2 + (co & 1);
            g_part[b * 16 + t] = (smp[wbase][r] + smp[wbase + 1][r])
                               + (smp[wbase + 2][r] + smp[wbase + 3][r]);
        }
    }
    gbar();

    // ================= stage 2: stats finalize + bn+relu + compaction =================
    if (b < 12) {
        int sl = b, c = sl / 3, base = sl * 4096;
        if (wid == 0) {
            float s3 = 0.f, q3 = 0.f, s1 = 0.f, q1 = 0.f;
            for (int bb = lane; bb < NB; bb += 32) {
                const float* P = g_part + bb * 16;
                s3 += P[c]; q3 += P[4 + c]; s1 += P[8 + c]; q1 += P[12 + c];
            }
            for (int o = 16; o > 0; o >>= 1) {
                s3 += __shfl_xor_sync(0xffffffffu, s3, o);
                q3 += __shfl_xor_sync(0xffffffffu, q3, o);
                s1 += __shfl_xor_sync(0xffffffffu, s1, o);
                q1 += __shfl_xor_sync(0xffffffffu, q1, o);
            }
            if (lane == 0) {
                float mean3 = s3 * (1.f / 12288.f);
                float var3  = q3 * (1.f / 12288.f) - mean3 * mean3;
                float sc3 = g3[c] * rsqrtf(var3 + 1e-5f);
                float mean1 = s1 * (1.f / 12288.f);
                float var1  = q1 * (1.f / 12288.f) - mean1 * mean1;
                float sc1 = g1[c] * rsqrtf(var1 + 1e-5f);
                shsc[0] = sc3; shsc[1] = be3[c] - mean3 * sc3;
                shsc[2] = sc1; shsc[3] = be1[c] - mean1 * sc1;
            }
        }
        __syncthreads();
        float sc3 = shsc[0], sh3 = shsc[1], sc1 = shsc[2], sh1v = shsc[3];

        float mx = 0.f, s0 = 0.f;
        int cnt = 0;
        int b0 = base + t * 16;
        #pragma unroll
        for (int k = 0; k < 16; k++) {
            int j = b0 + k;
            float q = fmaxf(fmaf(g_conv1[j], sc1, sh1v), 0.f);
            float v = fmaxf(fmaf(g_conv3[j], sc3, sh3),  0.f);
            g_q[j] = q; g_v[j] = v;
            mx = fmaxf(mx, q);
            if (q > 0.f) cnt++; else s0 += v;
        }
        float m2 = mx, z2 = s0;
        for (int o = 16; o > 0; o >>= 1) {
            m2 = fmaxf(m2, __shfl_xor_sync(0xffffffffu, m2, o));
            z2 += __shfl_xor_sync(0xffffffffu, z2, o);
        }
        int inc = cnt;
        #pragma unroll
        for (int o = 1; o < 32; o <<= 1) {
            int nn = __shfl_up_sync(0xffffffffu, inc, o);
            if (lane >= o) inc += nn;
        }
        if (lane == 31) shw[wid] = inc;
        if (lane == 0) { shf[wid] = m2; shs[wid] = z2; }
        __syncthreads();
        if (wid == 0 && lane < 8) {
            int sv = shw[lane];
            #pragma unroll
            for (int o = 1; o < 8; o <<= 1) {
                int nn = __shfl_up_sync(0xffu, sv, o);
                if (lane >= o) sv += nn;
            }
            shw[lane] = sv;
            float fm = shf[lane], fz = shs[lane];
            for (int o = 4; o > 0; o >>= 1) {
                fm = fmaxf(fm, __shfl_xor_sync(0xffu, fm, o));
                fz += __shfl_xor_sync(0xffu, fz, o);
            }
            if (lane == 0) { shf[0] = fm; shs[0] = fz; }
        }
        __syncthreads();
        int off = (wid ? shw[wid - 1] : 0) + inc - cnt;
        #pragma unroll
        for (int k = 0; k < 16; k++) {
            int j = b0 + k;
            float q = g_q[j];
            if (q > 0.f) {
                g_A[sl][off]   = q;
                g_Vnz[sl][off] = g_v[j];
                off++;
            }
        }
        if (t == 0) {
            g_m[sl]    = shw[7];
            g_qmax[sl] = shf[0];
            g_s0n[sl]  = shs[0] * (1.f / 4096.f);
        }
    }
    gbar();

    // ================= stage 3: F(t_k) partials =================
    {
        int sl = b >> 3, ch = b & 7;
        int m = g_m[sl];
        int chunk = (m + 7) >> 3;
        int j0 = ch * chunk;
        int n = m - j0; if (n > chunk) n = chunk; if (n < 0) n = 0;
        for (int i = t; i < n; i += NT) shA[i] = g_A[sl][j0 + i];
        __syncthreads();

        int k = t & 63, ln = t >> 6;
        float qmax = g_qmax[sl];
        float tl = (float)k * (qmax * (1.f / (KG - 1))) * LOG2E;
        float cn = -qmax * tl;
        float a0 = 0.f, a1 = 0.f;
        int i = ln;
        for (; i + 4 < n; i += 8) {
            a0 += ex2(fmaf(shA[i],     tl, cn));
            a1 += ex2(fmaf(shA[i + 4], tl, cn));
        }
        for (; i < n; i += 4) a0 += ex2(fmaf(shA[i], tl, cn));
        shP[ln][k] = a0 + a1;
        __syncthreads();
        if (t < KG)
            g_Fp[sl][ch][t] = (shP[0][t] + shP[1][t]) + (shP[2][t] + shP[3][t]);
    }
    gbar();

    // ================= stage 4: reduce F + chunk U + G(t_k) partials =================
    {
        int sl = b >> 3, ch = b & 7;
        int m = g_m[sl];
        float qmax = g_qmax[sl];
        if (t < KG) {
            float f = 0.f;
            #pragma unroll
            for (int j = 0; j < JS; j++) f += g_Fp[sl][j][t];
            float tk = (float)t * (qmax * (1.f / (KG - 1)));
            f += (float)(4096 - m) * ex2(-tk * qmax * LOG2E);
            shF[t] = f;
        }
        int chunk = (m + 7) >> 3;
        int j0 = ch * chunk;
        int n = m - j0; if (n > chunk) n = chunk; if (n < 0) n = 0;
        for (int i = t; i < n; i += NT) shA[i] = g_A[sl][j0 + i];
        __syncthreads();

        float inv = (qmax > 0.f) ? (float)(KG - 1) / qmax : 0.f;
        float bz = -qmax * LOG2E;
        for (int i = t; i < n; i += NT) {
            float q = shA[i];
            float u = q * inv;
            int k0 = min((int)u, KG - 2);
            float fr = u - (float)k0;
            float F = fmaf(shF[k0 + 1] - shF[k0], fr, shF[k0]);
            shU[i] = (g_Vnz[sl][j0 + i] / F) * ex2(q * bz);
        }
        __syncthreads();

        int k = t & 63, ln = t >> 6;
        float tl = (float)k * (qmax * (1.f / (KG - 1))) * LOG2E;
        float a0 = 0.f, a1 = 0.f;
        int i = ln;
        for (; i + 4 < n; i += 8) {
            a0 = fmaf(shU[i],     ex2(shA[i]     * tl), a0);
            a1 = fmaf(shU[i + 4], ex2(shA[i + 4] * tl), a1);
        }
        for (; i < n; i += 4) a0 = fmaf(shU[i], ex2(shA[i] * tl), a0);
        shP[ln][k] = a0 + a1;
        __syncthreads();
        if (t < KG)
            g_Gp[sl][ch][t] = (shP[0][t] + shP[1][t]) + (shP[2][t] + shP[3][t]);
    }
    gbar();

    // ================= stage 5: reduce G + Patt interp + Datt + epilogue =================
    if (b < 64) {
        int c = b >> 4;
        if (t < 3 * KG) {
            int d = t >> 6, k = t & (KG - 1);
            int sl = c * 3 + d;
            float s = 0.f;
            #pragma unroll
            for (int j = 0; j < JS; j++) s += g_Gp[sl][j][k];
            shG[d][k] = s;
        }
        __syncthreads();

        float inv[3], s0n[3];
        #pragma unroll
        for (int d = 0; d < 3; d++) {
            float qm = g_qmax[c * 3 + d];
            inv[d] = (qm > 0.f) ? (float)(KG - 1) / qm : 0.f;
            s0n[d] = g_s0n[c * 3 + d];
        }

        int p = (b & 15) * 256 + t;
        int base = c * 12288 + p;

        float qv[3], vv[3], patt[3];
        #pragma unroll
        for (int d = 0; d < 3; d++) {
            qv[d] = g_q[base + d * 4096];
            vv[d] = g_v[base + d * 4096];
            float u = qv[d] * inv[d];
            int k0 = min((int)u, KG - 2);
            float fr = u - (float)k0;
            patt[d] = fmaf(shG[d][k0 + 1] - shG[d][k0], fr, shG[d][k0]) + s0n[d];
        }

        float qm = fmaxf(qv[0], fmaxf(qv[1], qv[2]));
        float datt0 = 0.f, datt1 = 0.f, datt2 = 0.f;
        #pragma unroll
        for (int i = 0; i < 3; i++) {
            float e0 = ex2(qv[i] * (qv[0] - qm) * LOG2E);
            float e1 = ex2(qv[i] * (qv[1] - qm) * LOG2E);
            float e2 = ex2(qv[i] * (qv[2] - qm) * LOG2E);
            float rz = vv[i] / (e0 + e1 + e2);
            datt0 = fmaf(rz, e0, datt0);
            datt1 = fmaf(rz, e1, datt1);
            datt2 = fmaf(rz, e2, datt2);
        }
        float datt[3] = {datt0, datt1, datt2};
        float g = gama[0];
        #pragma unroll
        for (int d = 0; d < 3; d++) {
            int gi = base + d * 4096;
            out[gi] = fmaf(g, patt[d] + datt[d], x[gi]);
        }
    }
}

// ---------------- launch ----------------
extern "C" void kernel_launch(void* const* d_in, const int* in_sizes, int n_in,
                              void* d_out, int out_size) {
    const float* x    = (const float*)d_in[0];
    const float* W3   = (const float*)d_in[1];
    const float* b3   = (const float*)d_in[2];
    const float* g3   = (const float*)d_in[3];
    const float* be3  = (const float*)d_in[4];
    const float* W1   = (const float*)d_in[5];
    const float* b1   = (const float*)d_in[6];
    const float* g1   = (const float*)d_in[7];
    const float* be1  = (const float*)d_in[8];
    const float* gama = (const float*)d_in[9];
    float* out = (float*)d_out;

    fused_kernel<<<NB, NT>>>(x, W3, b3, g3, be3, W1, b1, g1, be1, gama, out);
}

// round 6
// speedup vs baseline: 1.0052x; 1.0052x over previous
#include <cuda_runtime.h>

#define LOG2E 1.4426950408889634f
#define KG 64            // interpolation grid size
#define JS 8             // j-chunks per slice for grid stages
#define NB 96            // persistent blocks (single wave, <=148 SMs)
#define NT 256

// ---------------- scratch ----------------
__device__ float g_conv3[49152];
__device__ float g_conv1[49152];
__device__ float g_v[49152];
__device__ float g_q[49152];
__device__ float g_part[NB * 16];  // per-block stats partials: s3[4] sq3[4] s1[4] sq1[4]
__device__ int   g_m[12];
__device__ float g_qmax[12];
__device__ float g_s0n[12];
__device__ float g_A[12][4096];
__device__ float g_Vnz[12][4096];
__device__ float g_Fp[12][JS][KG];
__device__ float g_Gp[12][JS][KG];
__device__ unsigned g_count;        // gbar arrival count (reset each launch)
__device__ unsigned g_gen;          // monotonic generation (+1 per launch)
__device__ unsigned g_prepf[12];    // monotonic: +1 per launch per slice
__device__ unsigned g_Ff[12];       // monotonic: +8 per launch per slice
__device__ unsigned g_Gf[12];       // monotonic: +8 per launch per slice

__device__ __forceinline__ float ex2(float x) {
    float y; asm("ex2.approx.ftz.f32 %0, %1;" : "=f"(y) : "f"(x)); return y;
}

// full grid barrier (used once): read gen, arrive, last resets count then bumps gen
__device__ __forceinline__ void gbar() {
    __syncthreads();
    if (threadIdx.x == 0) {
        __threadfence();
        unsigned my = *(volatile unsigned*)&g_gen;
        unsigned old = atomicAdd(&g_count, 1u);
        if (old == NB - 1) {
            *(volatile unsigned*)&g_count = 0;
            __threadfence();
            atomicAdd(&g_gen, 1u);
        } else {
            while (*(volatile unsigned*)&g_gen == my) {}
        }
        __threadfence();
    }
    __syncthreads();
}

// block-wide release: all prior block writes -> flag bump
__device__ __forceinline__ void release(unsigned* f) {
    __syncthreads();
    if (threadIdx.x == 0) { __threadfence(); atomicAdd(f, 1u); }
}
// block-wide acquire: spin until *f >= tgt
__device__ __forceinline__ void acquire(volatile unsigned* f, unsigned tgt) {
    if (threadIdx.x == 0) {
        while (*f < tgt) {}
        __threadfence();
    }
    __syncthreads();
}

__global__ void __launch_bounds__(NT, 1)
fused_kernel(const float* __restrict__ x, const float* __restrict__ W3,
             const float* __restrict__ b3, const float* __restrict__ g3,
             const float* __restrict__ be3, const float* __restrict__ W1,
             const float* __restrict__ b1, const float* __restrict__ g1,
             const float* __restrict__ be1, const float* __restrict__ gama,
             float* __restrict__ out) {
    __shared__ float shW3[432];
    __shared__ float shW1[16];
    __shared__ float shB[8];
    __shared__ float smp[8][8];
    __shared__ float shf[8], shs[8];
    __shared__ int   shw[8];
    __shared__ float shsc[4];
    __shared__ __align__(16) float shA[512];
    __shared__ __align__(16) float shU[512];
    __shared__ float shF[KG];
    __shared__ float shP[4][KG];
    __shared__ float shG[3][KG];

    int t = threadIdx.x, b = blockIdx.x;
    int lane = t & 31, wid = t >> 5;

    // ================= stage 1: conv3 + conv1 + stats partials =================
    for (int i = t; i < 432; i += NT) shW3[i] = W3[i];
    if (t < 16) shW1[t] = W1[t];
    if (t < 4)  shB[t] = b3[t];
    if (t >= 4 && t < 8) shB[t] = b1[t - 4];
    __syncthreads();

    {
        int pos = b * 128 + (t & 127);
        int half = t >> 7;            // 0: co {0,1}, 1: co {2,3}
        int co0 = half * 2;
        int d = pos >> 12, p = pos & 4095, h = p >> 6, w = p & 63;

        float acc0 = shB[co0], accA = shB[co0 + 1];
        float c10 = shB[4 + co0], c1A = shB[4 + co0 + 1];

        #pragma unroll
        for (int ci = 0; ci < 4; ci++) {
            const float* xp = x + ci * 12288;
            #pragma unroll
            for (int kd = 0; kd < 3; kd++) {
                int zd = d + kd - 1;
                if ((unsigned)zd >= 3u) continue;
                #pragma unroll
                for (int kh = 0; kh < 3; kh++) {
                    int zh = h + kh - 1;
                    if ((unsigned)zh >= 64u) continue;
                    #pragma unroll
                    for (int kw = 0; kw < 3; kw++) {
                        int zw = w + kw - 1;
                        if ((unsigned)zw >= 64u) continue;
                        float xv = xp[zd * 4096 + zh * 64 + zw];
                        int ki = kd * 9 + kh * 3 + kw;
                        acc0 = fmaf(shW3[(co0 * 4 + ci) * 27 + ki], xv, acc0);
                        accA = fmaf(shW3[((co0 + 1) * 4 + ci) * 27 + ki], xv, accA);
                    }
                }
            }
            float xc = xp[d * 4096 + p];
            c10 = fmaf(shW1[co0 * 4 + ci], xc, c10);
            c1A = fmaf(shW1[(co0 + 1) * 4 + ci], xc, c1A);
        }
        g_conv3[co0 * 12288 + pos]       = acc0;
        g_conv3[(co0 + 1) * 12288 + pos] = accA;
        g_conv1[co0 * 12288 + pos]       = c10;
        g_conv1[(co0 + 1) * 12288 + pos] = c1A;

        float red[8] = {acc0, accA, acc0 * acc0, accA * accA,
                        c10, c1A, c10 * c10, c1A * c1A};
        #pragma unroll
        for (int j = 0; j < 8; j++)
            for (int o = 16; o > 0; o >>= 1)
                red[j] += __shfl_xor_sync(0xffffffffu, red[j], o);
        if (lane == 0) {
            #pragma unroll
            for (int j = 0; j < 8; j++) smp[wid][j] = red[j];
        }
        __syncthreads();
        if (t < 16) {
            int kind = t >> 2, co = t & 3;
            int wbase = (co >> 1) * 4;
            int r = kind * 2 + (co & 1);
            g_part[b * 16 + t] = (smp[wbase][r] + smp[wbase + 1][r])
                               + (smp[wbase + 2][r] + smp[wbase + 3][r]);
        }
    }
    gbar();
    unsigned tgt = *(volatile unsigned*)&g_gen;   // stable per-launch epoch = L+1

    // ================= stage 2: stats finalize + bn+relu + compaction (blocks 0-11) =================
    if (b < 12) {
        int sl = b, c = sl / 3, base = sl * 4096;
        if (wid == 0) {
            float s3 = 0.f, q3 = 0.f, s1 = 0.f, q1 = 0.f;
            for (int bb = lane; bb < NB; bb += 32) {
                const float* P = g_part + bb * 16;
                s3 += P[c]; q3 += P[4 + c]; s1 += P[8 + c]; q1 += P[12 + c];
            }
            for (int o = 16; o > 0; o >>= 1) {
                s3 += __shfl_xor_sync(0xffffffffu, s3, o);
                q3 += __shfl_xor_sync(0xffffffffu, q3, o);
                s1 += __shfl_xor_sync(0xffffffffu, s1, o);
                q1 += __shfl_xor_sync(0xffffffffu, q1, o);
            }
            if (lane == 0) {
                float mean3 = s3 * (1.f / 12288.f);
                float var3  = q3 * (1.f / 12288.f) - mean3 * mean3;
                float sc3 = g3[c] * rsqrtf(var3 + 1e-5f);
                float mean1 = s1 * (1.f / 12288.f);
                float var1  = q1 * (1.f / 12288.f) - mean1 * mean1;
                float sc1 = g1[c] * rsqrtf(var1 + 1e-5f);
                shsc[0] = sc3; shsc[1] = be3[c] - mean3 * sc3;
                shsc[2] = sc1; shsc[3] = be1[c] - mean1 * sc1;
            }
        }
        __syncthreads();
        float sc3 = shsc[0], sh3 = shsc[1], sc1 = shsc[2], sh1v = shsc[3];

        float mx = 0.f, s0 = 0.f;
        int cnt = 0;
        int b0 = base + t * 16;
        #pragma unroll
        for (int k = 0; k < 16; k++) {
            int j = b0 + k;
            float q = fmaxf(fmaf(g_conv1[j], sc1, sh1v), 0.f);
            float v = fmaxf(fmaf(g_conv3[j], sc3, sh3),  0.f);
            g_q[j] = q; g_v[j] = v;
            mx = fmaxf(mx, q);
            if (q > 0.f) cnt++; else s0 += v;
        }
        float m2 = mx, z2 = s0;
        for (int o = 16; o > 0; o >>= 1) {
            m2 = fmaxf(m2, __shfl_xor_sync(0xffffffffu, m2, o));
            z2 += __shfl_xor_sync(0xffffffffu, z2, o);
        }
        int inc = cnt;
        #pragma unroll
        for (int o = 1; o < 32; o <<= 1) {
            int nn = __shfl_up_sync(0xffffffffu, inc, o);
            if (lane >= o) inc += nn;
        }
        if (lane == 31) shw[wid] = inc;
        if (lane == 0) { shf[wid] = m2; shs[wid] = z2; }
        __syncthreads();
        if (wid == 0 && lane < 8) {
            int sv = shw[lane];
            #pragma unroll
            for (int o = 1; o < 8; o <<= 1) {
                int nn = __shfl_up_sync(0xffu, sv, o);
                if (lane >= o) sv += nn;
            }
            shw[lane] = sv;
            float fm = shf[lane], fz = shs[lane];
            for (int o = 4; o > 0; o >>= 1) {
                fm = fmaxf(fm, __shfl_xor_sync(0xffu, fm, o));
                fz += __shfl_xor_sync(0xffu, fz, o);
            }
            if (lane == 0) { shf[0] = fm; shs[0] = fz; }
        }
        __syncthreads();
        int off = (wid ? shw[wid - 1] : 0) + inc - cnt;
        #pragma unroll
        for (int k = 0; k < 16; k++) {
            int j = b0 + k;
            float q = g_q[j];
            if (q > 0.f) {
                g_A[sl][off]   = q;
                g_Vnz[sl][off] = g_v[j];
                off++;
            }
        }
        if (t == 0) {
            g_m[sl]    = shw[7];
            g_qmax[sl] = shf[0];
            g_s0n[sl]  = shs[0] * (1.f / 4096.f);
        }
        release(&g_prepf[sl]);       // slice sl ready
    }

    // ================= stage 3: F(t_k) partials (all blocks; sl = b>>3) =================
    {
        int sl = b >> 3, ch = b & 7;
        acquire(&g_prepf[sl], tgt);

        int m = g_m[sl];
        int chunk = (m + 7) >> 3;
        int j0 = ch * chunk;
        int n = m - j0; if (n > chunk) n = chunk; if (n < 0) n = 0;
        for (int i = t; i < n; i += NT) shA[i] = g_A[sl][j0 + i];
        __syncthreads();

        int k = t & 63, ln = t >> 6;
        float qmax = g_qmax[sl];
        float tl = (float)k * (qmax * (1.f / (KG - 1))) * LOG2E;
        float cn = -qmax * tl;
        float a0 = 0.f, a1 = 0.f;
        int i = ln;
        for (; i + 4 < n; i += 8) {
            a0 += ex2(fmaf(shA[i],     tl, cn));
            a1 += ex2(fmaf(shA[i + 4], tl, cn));
        }
        for (; i < n; i += 4) a0 += ex2(fmaf(shA[i], tl, cn));
        shP[ln][k] = a0 + a1;
        __syncthreads();
        if (t < KG)
            g_Fp[sl][ch][t] = (shP[0][t] + shP[1][t]) + (shP[2][t] + shP[3][t]);
        release(&g_Ff[sl]);
    }

    // ================= stage 4: reduce F + chunk U + G(t_k) partials =================
    {
        int sl = b >> 3, ch = b & 7;
        acquire(&g_Ff[sl], 8u * tgt);

        int m = g_m[sl];
        float qmax = g_qmax[sl];
        if (t < KG) {
            float f = 0.f;
            #pragma unroll
            for (int j = 0; j < JS; j++) f += g_Fp[sl][j][t];
            float tk = (float)t * (qmax * (1.f / (KG - 1)));
            f += (float)(4096 - m) * ex2(-tk * qmax * LOG2E);
            shF[t] = f;
        }
        int chunk = (m + 7) >> 3;
        int j0 = ch * chunk;
        int n = m - j0; if (n > chunk) n = chunk; if (n < 0) n = 0;
        for (int i = t; i < n; i += NT) shA[i] = g_A[sl][j0 + i];
        __syncthreads();

        float inv = (qmax > 0.f) ? (float)(KG - 1) / qmax : 0.f;
        float bz = -qmax * LOG2E;
        for (int i = t; i < n; i += NT) {
            float q = shA[i];
            float u = q * inv;
            int k0 = min((int)u, KG - 2);
            float fr = u - (float)k0;
            float F = fmaf(shF[k0 + 1] - shF[k0], fr, shF[k0]);
            shU[i] = (g_Vnz[sl][j0 + i] / F) * ex2(q * bz);
        }
        __syncthreads();

        int k = t & 63, ln = t >> 6;
        float tl = (float)k * (qmax * (1.f / (KG - 1))) * LOG2E;
        float a0 = 0.f, a1 = 0.f;
        int i = ln;
        for (; i + 4 < n; i += 8) {
            a0 = fmaf(shU[i],     ex2(shA[i]     * tl), a0);
            a1 = fmaf(shU[i + 4], ex2(shA[i + 4] * tl), a1);
        }
        for (; i < n; i += 4) a0 = fmaf(shU[i], ex2(shA[i] * tl), a0);
        shP[ln][k] = a0 + a1;
        __syncthreads();
        if (t < KG)
            g_Gp[sl][ch][t] = (shP[0][t] + shP[1][t]) + (shP[2][t] + shP[3][t]);
        release(&g_Gf[sl]);
    }

    // ================= stage 5: reduce G + Patt interp + Datt + epilogue (blocks 0-63) =================
    if (b < 64) {
        int c = b >> 4;
        acquire(&g_Gf[c * 3 + 0], 8u * tgt);
        acquire(&g_Gf[c * 3 + 1], 8u * tgt);
        acquire(&g_Gf[c * 3 + 2], 8u * tgt);

        if (t < 3 * KG) {
            int d = t >> 6, k = t & (KG - 1);
            int sl = c * 3 + d;
            float s = 0.f;
            #pragma unroll
            for (int j = 0; j < JS; j++) s += g_Gp[sl][j][k];
            shG[d][k] = s;
        }
        __syncthreads();

        float inv[3], s0n[3];
        #pragma unroll
        for (int d = 0; d < 3; d++) {
            float qm = g_qmax[c * 3 + d];
            inv[d] = (qm > 0.f) ? (float)(KG - 1) / qm : 0.f;
            s0n[d] = g_s0n[c * 3 + d];
        }

        int p = (b & 15) * 256 + t;
        int base = c * 12288 + p;

        float qv[3], vv[3], patt[3];
        #pragma unroll
        for (int d = 0; d < 3; d++) {
            qv[d] = g_q[base + d * 4096];
            vv[d] = g_v[base + d * 4096];
            float u = qv[d] * inv[d];
            int k0 = min((int)u, KG - 2);
            float fr = u - (float)k0;
            patt[d] = fmaf(shG[d][k0 + 1] - shG[d][k0], fr, shG[d][k0]) + s0n[d];
        }

        float qm = fmaxf(qv[0], fmaxf(qv[1], qv[2]));
        float datt0 = 0.f, datt1 = 0.f, datt2 = 0.f;
        #pragma unroll
        for (int i = 0; i < 3; i++) {
            float e0 = ex2(qv[i] * (qv[0] - qm) * LOG2E);
            float e1 = ex2(qv[i] * (qv[1] - qm) * LOG2E);
            float e2 = ex2(qv[i] * (qv[2] - qm) * LOG2E);
            float rz = vv[i] / (e0 + e1 + e2);
            datt0 = fmaf(rz, e0, datt0);
            datt1 = fmaf(rz, e1, datt1);
            datt2 = fmaf(rz, e2, datt2);
        }
        float datt[3] = {datt0, datt1, datt2};
        float g = gama[0];
        #pragma unroll
        for (int d = 0; d < 3; d++) {
            int gi = base + d * 4096;
            out[gi] = fmaf(g, patt[d] + datt[d], x[gi]);
        }
    }
}

// ---------------- launch ----------------
extern "C" void kernel_launch(void* const* d_in, const int* in_sizes, int n_in,
                              void* d_out, int out_size) {
    const float* x    = (const float*)d_in[0];
    const float* W3   = (const float*)d_in[1];
    const float* b3   = (const float*)d_in[2];
    const float* g3   = (const float*)d_in[3];
    const float* be3  = (const float*)d_in[4];
    const float* W1   = (const float*)d_in[5];
    const float* b1   = (const float*)d_in[6];
    const float* g1   = (const float*)d_in[7];
    const float* be1  = (const float*)d_in[8];
    const float* gama = (const float*)d_in[9];
    float* out = (float*)d_out;

    fused_kernel<<<NB, NT>>>(x, W3, b3, g3, be3, W1, b1, g1, be1, gama, out);
}

// round 7
// speedup vs baseline: 1.2006x; 1.1944x over previous
#include <cuda_runtime.h>

#define LOG2E 1.4426950408889634f
#define KB 64            // bins == interpolation grid points
#define NB 96            // persistent blocks (single wave)
#define NT 512

// ---------------- scratch ----------------
__device__ float g_conv3[49152];
__device__ float g_conv1[49152];
__device__ float g_v[49152];
__device__ float g_q[49152];
__device__ float g_part[NB * 16];  // [kind*4 + co]: s3,sq3,s1,sq1
__device__ float g_qmax[12];
__device__ float g_s0n[12];
__device__ float g_G[12][KB];      // final G tables
__device__ unsigned g_count;       // gbar arrivals
__device__ unsigned g_gen;         // +1 per launch (monotonic)
__device__ unsigned g_slicef[12];  // +1 per launch per slice (monotonic)

__device__ __forceinline__ float ex2(float x) {
    float y; asm("ex2.approx.ftz.f32 %0, %1;" : "=f"(y) : "f"(x)); return y;
}

__device__ __forceinline__ void gbar() {
    __syncthreads();
    if (threadIdx.x == 0) {
        __threadfence();
        unsigned my = *(volatile unsigned*)&g_gen;
        unsigned old = atomicAdd(&g_count, 1u);
        if (old == NB - 1) {
            *(volatile unsigned*)&g_count = 0;
            __threadfence();
            atomicAdd(&g_gen, 1u);
        } else {
            while (*(volatile unsigned*)&g_gen == my) {}
        }
        __threadfence();
    }
    __syncthreads();
}

__device__ __forceinline__ void release(unsigned* f) {
    __syncthreads();
    if (threadIdx.x == 0) { __threadfence(); atomicAdd(f, 1u); }
}
__device__ __forceinline__ void acquire(volatile unsigned* f, unsigned tgt) {
    if (threadIdx.x == 0) {
        while (*f < tgt) {}
        __threadfence();
    }
    __syncthreads();
}

__global__ void __launch_bounds__(NT, 1)
fused_kernel(const float* __restrict__ x, const float* __restrict__ W3,
             const float* __restrict__ b3, const float* __restrict__ g3,
             const float* __restrict__ be3, const float* __restrict__ W1,
             const float* __restrict__ b1, const float* __restrict__ g1,
             const float* __restrict__ be1, const float* __restrict__ gama,
             float* __restrict__ out) {
    __shared__ float shW3[432];
    __shared__ float shW1[16];
    __shared__ float shB[8];
    __shared__ float smp[16][4];
    __shared__ float shf[16], shs[16];
    __shared__ int   shi[16];
    __shared__ float shsc[4];
    __shared__ float shHW[16 * 66];    // per-warp histograms (stride 66)
    __shared__ float shC[KB];          // reduced histogram
    __shared__ float shHt[KB];         // H table
    __shared__ float shG[3][KB];       // final-stage G tables

    int t = threadIdx.x, b = blockIdx.x;
    int lane = t & 31, wid = t >> 5;

    // ================= stage 1: conv3 + conv1 (one co per thread) + stats partials =================
    for (int i = t; i < 432; i += NT) shW3[i] = W3[i];
    if (t < 16) shW1[t] = W1[t];
    if (t < 4)  shB[t] = b3[t];
    if (t >= 4 && t < 8) shB[t] = b1[t - 4];
    __syncthreads();

    {
        int pos = b * 128 + (t & 127);
        int co = t >> 7;                       // 0..3
        int d = pos >> 12, p = pos & 4095, h = p >> 6, w = p & 63;

        float acc3 = shB[co], acc1 = shB[4 + co];
        #pragma unroll
        for (int ci = 0; ci < 4; ci++) {
            const float* xp = x + ci * 12288;
            const float* wp = shW3 + (co * 4 + ci) * 27;
            #pragma unroll
            for (int kd = 0; kd < 3; kd++) {
                int zd = d + kd - 1;
                if ((unsigned)zd >= 3u) continue;
                #pragma unroll
                for (int kh = 0; kh < 3; kh++) {
                    int zh = h + kh - 1;
                    if ((unsigned)zh >= 64u) continue;
                    #pragma unroll
                    for (int kw = 0; kw < 3; kw++) {
                        int zw = w + kw - 1;
                        if ((unsigned)zw >= 64u) continue;
                        acc3 = fmaf(wp[kd * 9 + kh * 3 + kw],
                                    xp[zd * 4096 + zh * 64 + zw], acc3);
                    }
                }
            }
            acc1 = fmaf(shW1[co * 4 + ci], xp[d * 4096 + p], acc1);
        }
        g_conv3[co * 12288 + pos] = acc3;
        g_conv1[co * 12288 + pos] = acc1;

        float red[4] = {acc3, acc3 * acc3, acc1, acc1 * acc1};
        #pragma unroll
        for (int j = 0; j < 4; j++)
            for (int o = 16; o > 0; o >>= 1)
                red[j] += __shfl_xor_sync(0xffffffffu, red[j], o);
        if (lane == 0) {
            #pragma unroll
            for (int j = 0; j < 4; j++) smp[wid][j] = red[j];
        }
        __syncthreads();
        if (t < 16) {
            int co2 = t >> 2, kind = t & 3;      // warps co2*4 .. co2*4+3
            int w0 = co2 * 4;
            g_part[b * 16 + kind * 4 + co2] =
                (smp[w0][kind] + smp[w0 + 1][kind]) + (smp[w0 + 2][kind] + smp[w0 + 3][kind]);
        }
    }
    gbar();
    unsigned tgt = *(volatile unsigned*)&g_gen;    // per-launch epoch

    // ================= stage 2: per-slice block does EVERYTHING (blocks 0-11) =================
    if (b < 12) {
        int sl = b, c = sl / 3, base = sl * 4096;

        // stats finalize (warp 0)
        if (wid == 0) {
            float s3 = 0.f, q3 = 0.f, s1 = 0.f, q1 = 0.f;
            for (int bb = lane; bb < NB; bb += 32) {
                const float* P = g_part + bb * 16;
                s3 += P[c]; q3 += P[4 + c]; s1 += P[8 + c]; q1 += P[12 + c];
            }
            for (int o = 16; o > 0; o >>= 1) {
                s3 += __shfl_xor_sync(0xffffffffu, s3, o);
                q3 += __shfl_xor_sync(0xffffffffu, q3, o);
                s1 += __shfl_xor_sync(0xffffffffu, s1, o);
                q1 += __shfl_xor_sync(0xffffffffu, q1, o);
            }
            if (lane == 0) {
                float mean3 = s3 * (1.f / 12288.f);
                float var3  = q3 * (1.f / 12288.f) - mean3 * mean3;
                float sc3 = g3[c] * rsqrtf(var3 + 1e-5f);
                float mean1 = s1 * (1.f / 12288.f);
                float var1  = q1 * (1.f / 12288.f) - mean1 * mean1;
                float sc1 = g1[c] * rsqrtf(var1 + 1e-5f);
                shsc[0] = sc3; shsc[1] = be3[c] - mean3 * sc3;
                shsc[2] = sc1; shsc[3] = be1[c] - mean1 * sc1;
            }
        }
        __syncthreads();
        float sc3 = shsc[0], sh3 = shsc[1], sc1 = shsc[2], sh1v = shsc[3];

        // pass 1: bn+relu, keep 8 elems in regs; qmax / zero-v sum / nonzero count
        float qv[8], vv[8];
        float mx = 0.f, s0 = 0.f;
        int cnt = 0;
        int b0 = base + t * 8;
        #pragma unroll
        for (int k = 0; k < 8; k++) {
            int j = b0 + k;
            float q = fmaxf(fmaf(g_conv1[j], sc1, sh1v), 0.f);
            float v = fmaxf(fmaf(g_conv3[j], sc3, sh3),  0.f);
            g_q[j] = q; g_v[j] = v;
            qv[k] = q; vv[k] = v;
            mx = fmaxf(mx, q);
            if (q > 0.f) cnt++; else s0 += v;
        }
        for (int o = 16; o > 0; o >>= 1) {
            mx = fmaxf(mx, __shfl_xor_sync(0xffffffffu, mx, o));
            s0 += __shfl_xor_sync(0xffffffffu, s0, o);
            cnt += __shfl_xor_sync(0xffffffffu, cnt, o);
        }
        if (lane == 0) { shf[wid] = mx; shs[wid] = s0; shi[wid] = cnt; }
        __syncthreads();
        if (wid == 0 && lane < 16) {
            float fm = shf[lane], fz = shs[lane];
            int fc = shi[lane];
            for (int o = 8; o > 0; o >>= 1) {
                fm = fmaxf(fm, __shfl_xor_sync(0xffffu, fm, o));
                fz += __shfl_xor_sync(0xffffu, fz, o);
                fc += __shfl_xor_sync(0xffffu, fc, o);
            }
            if (lane == 0) { shf[0] = fm; shs[0] = fz; shi[0] = fc; }
        }
        __syncthreads();
        float qmax = shf[0];
        int   m    = shi[0];
        float s0n  = shs[0] * (1.f / 4096.f);
        float inv  = (qmax > 0.f) ? (float)(KB - 1) / qmax : 0.f;
        float step = qmax * (1.f / (KB - 1));

        // histogram counts (linear binning, per-warp hists)
        for (int i = t; i < 16 * 66; i += NT) shHW[i] = 0.f;
        __syncthreads();
        float* myh = shHW + wid * 66;
        #pragma unroll
        for (int k = 0; k < 8; k++) {
            float q = qv[k];
            if (q > 0.f) {
                float u = q * inv;
                int k0 = min((int)u, KB - 2);
                float fr = u - (float)k0;
                atomicAdd(myh + k0, 1.f - fr);
                atomicAdd(myh + k0 + 1, fr);
            }
        }
        __syncthreads();
        if (t < KB) {
            float s = 0.f;
            #pragma unroll
            for (int w = 0; w < 16; w++) s += shHW[w * 66 + t];
            shC[t] = s;
        }
        __syncthreads();

        // F table + H table (threads 0..63)
        if (t < KB) {
            float tl = (float)t * step * LOG2E;
            float cn = -qmax * tl;
            float F = 0.f;
            #pragma unroll 8
            for (int bb = 0; bb < KB; bb++)
                F = fmaf(shC[bb], ex2(fmaf((float)bb * step, tl, cn)), F);
            float z = ex2(cn);
            F += (float)(4096 - m) * z;
            shHt[t] = z / F;
        }
        __syncthreads();

        // pass 2: u_i = v_i * H(q_i), histogram into U_b
        for (int i = t; i < 16 * 66; i += NT) shHW[i] = 0.f;
        __syncthreads();
        #pragma unroll
        for (int k = 0; k < 8; k++) {
            float q = qv[k];
            if (q > 0.f) {
                float u = q * inv;
                int k0 = min((int)u, KB - 2);
                float fr = u - (float)k0;
                float H = fmaf(shHt[k0 + 1] - shHt[k0], fr, shHt[k0]);
                float uu = vv[k] * H;
                atomicAdd(myh + k0, uu * (1.f - fr));
                atomicAdd(myh + k0 + 1, uu * fr);
            }
        }
        __syncthreads();
        if (t < KB) {
            float s = 0.f;
            #pragma unroll
            for (int w = 0; w < 16; w++) s += shHW[w * 66 + t];
            shC[t] = s;
        }
        __syncthreads();

        // G table
        if (t < KB) {
            float tl = (float)t * step * LOG2E;
            float G = 0.f;
            #pragma unroll 8
            for (int bb = 0; bb < KB; bb++)
                G = fmaf(shC[bb], ex2((float)bb * step * tl), G);
            g_G[sl][t] = G;
        }
        if (t == 0) { g_qmax[sl] = qmax; g_s0n[sl] = s0n; }
        release(&g_slicef[sl]);
    }

    // ================= stage 3: Patt interp + Datt + epilogue (blocks 0-31) =================
    if (b < 32) {
        int c = b >> 3;                          // 8 blocks per channel
        acquire(&g_slicef[c * 3 + 0], tgt);
        acquire(&g_slicef[c * 3 + 1], tgt);
        acquire(&g_slicef[c * 3 + 2], tgt);

        if (t < 3 * KB) {
            int d = t >> 6, k = t & (KB - 1);
            shG[d][k] = g_G[c * 3 + d][k];
        }
        __syncthreads();

        float inv3[3], s0n3[3];
        #pragma unroll
        for (int d = 0; d < 3; d++) {
            float qm = g_qmax[c * 3 + d];
            inv3[d] = (qm > 0.f) ? (float)(KB - 1) / qm : 0.f;
            s0n3[d] = g_s0n[c * 3 + d];
        }

        int p = (b & 7) * 512 + t;
        int base = c * 12288 + p;

        float qv[3], vv[3], patt[3];
        #pragma unroll
        for (int d = 0; d < 3; d++) {
            qv[d] = g_q[base + d * 4096];
            vv[d] = g_v[base + d * 4096];
            float u = qv[d] * inv3[d];
            int k0 = min((int)u, KB - 2);
            float fr = u - (float)k0;
            patt[d] = fmaf(shG[d][k0 + 1] - shG[d][k0], fr, shG[d][k0]) + s0n3[d];
        }

        float qm = fmaxf(qv[0], fmaxf(qv[1], qv[2]));
        float datt0 = 0.f, datt1 = 0.f, datt2 = 0.f;
        #pragma unroll
        for (int i = 0; i < 3; i++) {
            float e0 = ex2(qv[i] * (qv[0] - qm) * LOG2E);
            float e1 = ex2(qv[i] * (qv[1] - qm) * LOG2E);
            float e2 = ex2(qv[i] * (qv[2] - qm) * LOG2E);
            float rz = vv[i] / (e0 + e1 + e2);
            datt0 = fmaf(rz, e0, datt0);
            datt1 = fmaf(rz, e1, datt1);
            datt2 = fmaf(rz, e2, datt2);
        }
        float datt[3] = {datt0, datt1, datt2};
        float g = gama[0];
        #pragma unroll
        for (int d = 0; d < 3; d++) {
            int gi = base + d * 4096;
            out[gi] = fmaf(g, patt[d] + datt[d], x[gi]);
        }
    }
}

// ---------------- launch ----------------
extern "C" void kernel_launch(void* const* d_in, const int* in_sizes, int n_in,
                              void* d_out, int out_size) {
    const float* x    = (const float*)d_in[0];
    const float* W3   = (const float*)d_in[1];
    const float* b3   = (const float*)d_in[2];
    const float* g3   = (const float*)d_in[3];
    const float* be3  = (const float*)d_in[4];
    const float* W1   = (const float*)d_in[5];
    const float* b1   = (const float*)d_in[6];
    const float* g1   = (const float*)d_in[7];
    const float* be1  = (const float*)d_in[8];
    const float* gama = (const float*)d_in[9];
    float* out = (float*)d_out;

    fused_kernel<<<NB, NT>>>(x, W3, b3, g3, be3, W1, b1, g1, be1, gama, out);
}

// round 8
// speedup vs baseline: 1.3620x; 1.1344x over previous
#include <cuda_runtime.h>

#define LOG2E 1.4426950408889634f
#define KB 64            // bins == interpolation grid points
#define NB 96            // persistent blocks (single wave)
#define NT 512

// ---------------- scratch ----------------
__device__ float g_conv3[49152];
__device__ float g_conv1[49152];
__device__ float g_part[NB * 16];  // [kind*4 + co]: s3,sq3,s1,sq1
__device__ float g_qmax[12];
__device__ float g_s0n[12];
__device__ float g_G[12][KB];      // final G tables
__device__ unsigned g_cnt[8];      // monotonic group arrival counters (+12/launch)
__device__ unsigned g_root;        // monotonic (+8/launch)
__device__ unsigned g_gen;         // epoch (+1/launch)
__device__ unsigned g_slicef[12];  // +1 per launch per slice (monotonic)

__device__ __forceinline__ float ex2(float x) {
    float y; asm("ex2.approx.ftz.f32 %0, %1;" : "=f"(y) : "f"(x)); return y;
}

// two-level grid barrier: groups of 12 -> root of 8 -> bump epoch
__device__ __forceinline__ void gbar2(int b) {
    __syncthreads();
    if (threadIdx.x == 0) {
        __threadfence();
        unsigned my = *(volatile unsigned*)&g_gen;
        int g = b / 12;
        unsigned old = atomicAdd(&g_cnt[g], 1u);
        if (old == 12u * (my + 1u) - 1u) {
            unsigned o2 = atomicAdd(&g_root, 1u);
            if (o2 == 8u * (my + 1u) - 1u) {
                __threadfence();
                atomicAdd(&g_gen, 1u);
            }
        }
        while (*(volatile unsigned*)&g_gen == my) {}
        __threadfence();
    }
    __syncthreads();
}

__device__ __forceinline__ void release(unsigned* f) {
    __syncthreads();
    if (threadIdx.x == 0) { __threadfence(); atomicAdd(f, 1u); }
}
__device__ __forceinline__ void acquire(volatile unsigned* f, unsigned tgt) {
    if (threadIdx.x == 0) {
        while (*f < tgt) {}
        __threadfence();
    }
    __syncthreads();
}

__global__ void __launch_bounds__(NT, 1)
fused_kernel(const float* __restrict__ x, const float* __restrict__ W3,
             const float* __restrict__ b3, const float* __restrict__ g3,
             const float* __restrict__ be3, const float* __restrict__ W1,
             const float* __restrict__ b1, const float* __restrict__ g1,
             const float* __restrict__ be1, const float* __restrict__ gama,
             float* __restrict__ out) {
    __shared__ float shW3[432];
    __shared__ float shW1[16];
    __shared__ float shB[8];
    __shared__ float smp[16][4];
    __shared__ float shf[16], shs[16];
    __shared__ int   shi[16];
    __shared__ float shsc[4];
    __shared__ float shHW[16 * 66];    // per-warp histograms (stride 66)
    __shared__ float shC[KB];          // reduced histogram
    __shared__ float shHt[KB];         // H table
    __shared__ float shP[8][KB];       // table-build partials
    __shared__ float shG[3][KB];       // final-stage G tables

    int t = threadIdx.x, b = blockIdx.x;
    int lane = t & 31, wid = t >> 5;

    // ================= stage 1: conv3 + conv1 (one co per thread) + stats partials =================
    for (int i = t; i < 432; i += NT) shW3[i] = W3[i];
    if (t < 16) shW1[t] = W1[t];
    if (t < 4)  shB[t] = b3[t];
    if (t >= 4 && t < 8) shB[t] = b1[t - 4];
    __syncthreads();

    {
        int pos = b * 128 + (t & 127);
        int co = t >> 7;                       // 0..3
        int d = pos >> 12, p = pos & 4095, h = p >> 6, w = p & 63;

        float acc3 = shB[co], acc1 = shB[4 + co];
        #pragma unroll
        for (int ci = 0; ci < 4; ci++) {
            const float* xp = x + ci * 12288;
            const float* wp = shW3 + (co * 4 + ci) * 27;
            #pragma unroll
            for (int kd = 0; kd < 3; kd++) {
                int zd = d + kd - 1;
                if ((unsigned)zd >= 3u) continue;
                #pragma unroll
                for (int kh = 0; kh < 3; kh++) {
                    int zh = h + kh - 1;
                    if ((unsigned)zh >= 64u) continue;
                    #pragma unroll
                    for (int kw = 0; kw < 3; kw++) {
                        int zw = w + kw - 1;
                        if ((unsigned)zw >= 64u) continue;
                        acc3 = fmaf(wp[kd * 9 + kh * 3 + kw],
                                    xp[zd * 4096 + zh * 64 + zw], acc3);
                    }
                }
            }
            acc1 = fmaf(shW1[co * 4 + ci], xp[d * 4096 + p], acc1);
        }
        g_conv3[co * 12288 + pos] = acc3;
        g_conv1[co * 12288 + pos] = acc1;

        float red[4] = {acc3, acc3 * acc3, acc1, acc1 * acc1};
        #pragma unroll
        for (int j = 0; j < 4; j++)
            for (int o = 16; o > 0; o >>= 1)
                red[j] += __shfl_xor_sync(0xffffffffu, red[j], o);
        if (lane == 0) {
            #pragma unroll
            for (int j = 0; j < 4; j++) smp[wid][j] = red[j];
        }
        __syncthreads();
        if (t < 16) {
            int co2 = t >> 2, kind = t & 3;
            int w0 = co2 * 4;
            g_part[b * 16 + kind * 4 + co2] =
                (smp[w0][kind] + smp[w0 + 1][kind]) + (smp[w0 + 2][kind] + smp[w0 + 3][kind]);
        }
    }
    gbar2(b);
    unsigned tgt = *(volatile unsigned*)&g_gen;    // per-launch epoch

    if (b >= 44) return;

    // -------- stats finalize for this block's channel (warp 0 -> shsc), identical math everywhere --------
    {
        int c = (b < 12) ? (b / 3) : ((b - 12) >> 3);
        if (wid == 0) {
            float s3 = 0.f, q3 = 0.f, s1 = 0.f, q1 = 0.f;
            for (int bb = lane; bb < NB; bb += 32) {
                const float* P = g_part + bb * 16;
                s3 += P[c]; q3 += P[4 + c]; s1 += P[8 + c]; q1 += P[12 + c];
            }
            for (int o = 16; o > 0; o >>= 1) {
                s3 += __shfl_xor_sync(0xffffffffu, s3, o);
                q3 += __shfl_xor_sync(0xffffffffu, q3, o);
                s1 += __shfl_xor_sync(0xffffffffu, s1, o);
                q1 += __shfl_xor_sync(0xffffffffu, q1, o);
            }
            if (lane == 0) {
                float mean3 = s3 * (1.f / 12288.f);
                float var3  = q3 * (1.f / 12288.f) - mean3 * mean3;
                float sc3 = g3[c] * rsqrtf(var3 + 1e-5f);
                float mean1 = s1 * (1.f / 12288.f);
                float var1  = q1 * (1.f / 12288.f) - mean1 * mean1;
                float sc1 = g1[c] * rsqrtf(var1 + 1e-5f);
                shsc[0] = sc3; shsc[1] = be3[c] - mean3 * sc3;
                shsc[2] = sc1; shsc[3] = be1[c] - mean1 * sc1;
            }
        }
        __syncthreads();
    }
    float sc3 = shsc[0], sh3 = shsc[1], sc1 = shsc[2], sh1v = shsc[3];

    // ================= slice blocks (0-11): histograms -> F -> H -> U -> G =================
    if (b < 12) {
        int sl = b, base = sl * 4096;

        // pass 1: bn+relu into regs; qmax / zero-v sum / nonzero count
        float qv[8], vv[8];
        float mx = 0.f, s0 = 0.f;
        int cnt = 0;
        int b0 = base + t * 8;
        #pragma unroll
        for (int k = 0; k < 8; k++) {
            int j = b0 + k;
            float q = fmaxf(fmaf(g_conv1[j], sc1, sh1v), 0.f);
            float v = fmaxf(fmaf(g_conv3[j], sc3, sh3),  0.f);
            qv[k] = q; vv[k] = v;
            mx = fmaxf(mx, q);
            if (q > 0.f) cnt++; else s0 += v;
        }
        for (int o = 16; o > 0; o >>= 1) {
            mx = fmaxf(mx, __shfl_xor_sync(0xffffffffu, mx, o));
            s0 += __shfl_xor_sync(0xffffffffu, s0, o);
            cnt += __shfl_xor_sync(0xffffffffu, cnt, o);
        }
        if (lane == 0) { shf[wid] = mx; shs[wid] = s0; shi[wid] = cnt; }
        __syncthreads();
        if (wid == 0 && lane < 16) {
            float fm = shf[lane], fz = shs[lane];
            int fc = shi[lane];
            for (int o = 8; o > 0; o >>= 1) {
                fm = fmaxf(fm, __shfl_xor_sync(0xffffu, fm, o));
                fz += __shfl_xor_sync(0xffffu, fz, o);
                fc += __shfl_xor_sync(0xffffu, fc, o);
            }
            if (lane == 0) { shf[0] = fm; shs[0] = fz; shi[0] = fc; }
        }
        __syncthreads();
        float qmax = shf[0];
        int   m    = shi[0];
        float s0n  = shs[0] * (1.f / 4096.f);
        float inv  = (qmax > 0.f) ? (float)(KB - 1) / qmax : 0.f;
        float step = qmax * (1.f / (KB - 1));

        // count histogram (linear binning, per-warp hists)
        for (int i = t; i < 16 * 66; i += NT) shHW[i] = 0.f;
        __syncthreads();
        float* myh = shHW + wid * 66;
        #pragma unroll
        for (int k = 0; k < 8; k++) {
            float q = qv[k];
            if (q > 0.f) {
                float u = q * inv;
                int k0 = min((int)u, KB - 2);
                float fr = u - (float)k0;
                atomicAdd(myh + k0, 1.f - fr);
                atomicAdd(myh + k0 + 1, fr);
            }
        }
        __syncthreads();
        if (t < KB) {
            float s = 0.f;
            #pragma unroll
            for (int w = 0; w < 16; w++) s += shHW[w * 66 + t];
            shC[t] = s;
        }
        __syncthreads();

        // F table (512 threads: 8-way bin split), then H
        {
            int k = t & 63, part = t >> 6;
            float tl = (float)k * step * LOG2E;
            float cn = -qmax * tl;
            float F = 0.f;
            int bb0 = part * 8;
            #pragma unroll
            for (int bb = 0; bb < 8; bb++)
                F = fmaf(shC[bb0 + bb], ex2(fmaf((float)(bb0 + bb) * step, tl, cn)), F);
            shP[part][k] = F;
        }
        __syncthreads();
        if (t < KB) {
            float F = ((shP[0][t] + shP[1][t]) + (shP[2][t] + shP[3][t]))
                    + ((shP[4][t] + shP[5][t]) + (shP[6][t] + shP[7][t]));
            float z = ex2(-(float)t * step * qmax * LOG2E);
            F += (float)(4096 - m) * z;
            shHt[t] = z / F;
        }
        __syncthreads();

        // pass 2: u_i = v_i * H(q_i), histogram into U_b
        for (int i = t; i < 16 * 66; i += NT) shHW[i] = 0.f;
        __syncthreads();
        #pragma unroll
        for (int k = 0; k < 8; k++) {
            float q = qv[k];
            if (q > 0.f) {
                float u = q * inv;
                int k0 = min((int)u, KB - 2);
                float fr = u - (float)k0;
                float H = fmaf(shHt[k0 + 1] - shHt[k0], fr, shHt[k0]);
                float uu = vv[k] * H;
                atomicAdd(myh + k0, uu * (1.f - fr));
                atomicAdd(myh + k0 + 1, uu * fr);
            }
        }
        __syncthreads();
        if (t < KB) {
            float s = 0.f;
            #pragma unroll
            for (int w = 0; w < 16; w++) s += shHW[w * 66 + t];
            shC[t] = s;
        }
        __syncthreads();

        // G table (8-way split)
        {
            int k = t & 63, part = t >> 6;
            float tl = (float)k * step * LOG2E;
            float G = 0.f;
            int bb0 = part * 8;
            #pragma unroll
            for (int bb = 0; bb < 8; bb++)
                G = fmaf(shC[bb0 + bb], ex2((float)(bb0 + bb) * step * tl), G);
            shP[part][k] = G;
        }
        __syncthreads();
        if (t < KB) {
            g_G[sl][t] = ((shP[0][t] + shP[1][t]) + (shP[2][t] + shP[3][t]))
                       + ((shP[4][t] + shP[5][t]) + (shP[6][t] + shP[7][t]));
        }
        if (t == 0) { g_qmax[sl] = qmax; g_s0n[sl] = s0n; }
        release(&g_slicef[sl]);
        return;
    }

    // ================= final blocks (12-43): q,v + Datt BEFORE waiting; then Patt =================
    {
        int fb = b - 12;
        int c = fb >> 3;
        int p = (fb & 7) * 512 + t;
        int base = c * 12288 + p;

        // bn+relu locally (identical scale math -> deterministic)
        float qv[3], vv[3];
        #pragma unroll
        for (int d = 0; d < 3; d++) {
            int j = base + d * 4096;
            qv[d] = fmaxf(fmaf(g_conv1[j], sc1, sh1v), 0.f);
            vv[d] = fmaxf(fmaf(g_conv3[j], sc3, sh3),  0.f);
        }

        // depth attention (independent of G tables)
        float qm = fmaxf(qv[0], fmaxf(qv[1], qv[2]));
        float datt0 = 0.f, datt1 = 0.f, datt2 = 0.f;
        #pragma unroll
        for (int i = 0; i < 3; i++) {
            float e0 = ex2(qv[i] * (qv[0] - qm) * LOG2E);
            float e1 = ex2(qv[i] * (qv[1] - qm) * LOG2E);
            float e2 = ex2(qv[i] * (qv[2] - qm) * LOG2E);
            float rz = vv[i] / (e0 + e1 + e2);
            datt0 = fmaf(rz, e0, datt0);
            datt1 = fmaf(rz, e1, datt1);
            datt2 = fmaf(rz, e2, datt2);
        }
        float datt[3] = {datt0, datt1, datt2};
        float xr[3];
        #pragma unroll
        for (int d = 0; d < 3; d++) xr[d] = x[base + d * 4096];
        float g = gama[0];

        // now wait for this channel's G tables
        acquire(&g_slicef[c * 3 + 0], tgt);
        acquire(&g_slicef[c * 3 + 1], tgt);
        acquire(&g_slicef[c * 3 + 2], tgt);

        if (t < 3 * KB) {
            int d = t >> 6, k = t & (KB - 1);
            shG[d][k] = g_G[c * 3 + d][k];
        }
        __syncthreads();

        #pragma unroll
        for (int d = 0; d < 3; d++) {
            int sl = c * 3 + d;
            float qmx = g_qmax[sl];
            float invd = (qmx > 0.f) ? (float)(KB - 1) / qmx : 0.f;
            float u = qv[d] * invd;
            int k0 = min((int)u, KB - 2);
            float fr = u - (float)k0;
            float patt = fmaf(shG[d][k0 + 1] - shG[d][k0], fr, shG[d][k0]) + g_s0n[sl];
            out[base + d * 4096] = fmaf(g, patt + datt[d], xr[d]);
        }
    }
}

// ---------------- launch ----------------
extern "C" void kernel_launch(void* const* d_in, const int* in_sizes, int n_in,
                              void* d_out, int out_size) {
    const float* x    = (const float*)d_in[0];
    const float* W3   = (const float*)d_in[1];
    const float* b3   = (const float*)d_in[2];
    const float* g3   = (const float*)d_in[3];
    const float* be3  = (const float*)d_in[4];
    const float* W1   = (const float*)d_in[5];
    const float* b1   = (const float*)d_in[6];
    const float* g1   = (const float*)d_in[7];
    const float* be1  = (const float*)d_in[8];
    const float* gama = (const float*)d_in[9];
    float* out = (float*)d_out;

    fused_kernel<<<NB, NT>>>(x, W3, b3, g3, be3, W1, b1, g1, be1, gama, out);
}